// round 14
// baseline (speedup 1.0000x reference)
#include <cuda_runtime.h>
#include <cfloat>
#include <math.h>

#define NPIL 30000
#define MPTS 32
#define NBLK 740
#define PPB  41                       // 740*41 = 30340 >= 30000
#define NMTOT (30000.0f * 32.0f)
#define LOG2E 1.4426950408889634f

// ---------------- globals (zero-init; counters reset by last block) ----------------
__device__ double   g_mom[65];
__device__ unsigned g_arrive;
__device__ unsigned g_done;

// QQ triangular index tables (l-38 -> (a,b))
__constant__ signed char d_qa[21] = {0,0,0,0,0,0,1,1,1,1,1,2,2,2,2,3,3,3,4,4,5};
__constant__ signed char d_qb[21] = {0,1,2,3,4,5,1,2,3,4,5,2,3,4,5,3,4,5,4,5,5};

__device__ __forceinline__ float ex2f(float x) {
    float y; asm("ex2.approx.f32 %0, %1;" : "=f"(y) : "f"(x)); return y;
}
__device__ __forceinline__ float wredsum(float v) {
#pragma unroll
    for (int o = 16; o; o >>= 1) v += __shfl_xor_sync(0xffffffffu, v, o);
    return v;
}
__device__ __forceinline__ float wredmax(float v) {
#pragma unroll
    for (int o = 16; o; o >>= 1) v = fmaxf(v, __shfl_xor_sync(0xffffffffu, v, o));
    return v;
}
__device__ __forceinline__ float wredmin(float v) {
#pragma unroll
    for (int o = 16; o; o >>= 1) v = fminf(v, __shfl_xor_sync(0xffffffffu, v, o));
    return v;
}

// moment-tail: value for red slot l (14..64); sqw[0..5]=q6, sqw[6..9]=Sv
__device__ __forceinline__ float tail_val(int l, const float* sqw, float fm) {
    if (l < 38) { int u = l - 14; return sqw[u >> 2] * sqw[6 + (u & 3)]; }
    if (l < 59) { int u = l - 38; return fm * sqw[(int)d_qa[u]] * sqw[(int)d_qb[u]]; }
    return fm * sqw[l - 59];
}

// ---------------- single persistent kernel ----------------
__global__ __launch_bounds__(256, 5) void k_fused(
    const float4* __restrict__ feat, const int* __restrict__ npts,
    const int4*  __restrict__ coors, float* __restrict__ out,
    const float* __restrict__ wq, const float* __restrict__ wk,
    const float* __restrict__ wv, const float* __restrict__ wo,
    const float* __restrict__ bq, const float* __restrict__ bk,
    const float* __restrict__ bv, const float* __restrict__ bo,
    const float* __restrict__ pfn_w,
    const float* __restrict__ gamma, const float* __restrict__ beta)
{
    __shared__ __align__(16) float4 s_feat[PPB][32];   // 20992 B
    __shared__ float  s_w[PPB][32];                    //  5248 B
    __shared__ float  s_cst[PPB][10];                  //  1640 B  q6[6],{wmmx,wmmy,fm},Sv3
    __shared__ __align__(16) float u_kvs[8][32][8];    //  8192 B  (phase A temp | fold arrays)
    __shared__ float  red[8][65];                      //  2080 B
    __shared__ float  swt[48];                         //   192 B

    const int tid  = threadIdx.x;
    const int wl   = tid >> 5;
    const int lane = tid & 31;
    const int base = blockIdx.x * PPB;
    const int rem  = NPIL - base;
    const int P    = rem > 0 ? (rem < PPB ? rem : PPB) : 0;

    {   // stage small weights
        int t = tid;
        if      (t <  9) swt[t] = wq[t];
        else if (t < 18) swt[t] = wk[t - 9];
        else if (t < 27) swt[t] = wv[t - 18];
        else if (t < 36) swt[t] = wo[t - 27];
        else if (t < 39) swt[t] = bq[t - 36];
        else if (t < 42) swt[t] = bk[t - 39];
        else if (t < 45) swt[t] = bv[t - 42];
        else if (t < 48) swt[t] = bo[t - 45];
    }
    __syncthreads();

    // ================= PHASE A: attention + moments, park data in smem =================
    float a0 = 0.f, a1 = 0.f, a2 = 0.f;

#pragma unroll 1
    for (int slot = wl; slot < P; slot += 8) {
        const int n = base + slot;
        float4 f = feat[n * MPTS + lane];
        const float x = f.x, y = f.y, z = f.z, I = f.w;
        s_feat[slot][lane] = f;

        float q0 = fmaf(x, swt[0], fmaf(y, swt[3], fmaf(z, swt[6], swt[36])));
        float q1 = fmaf(x, swt[1], fmaf(y, swt[4], fmaf(z, swt[7], swt[37])));
        float q2 = fmaf(x, swt[2], fmaf(y, swt[5], fmaf(z, swt[8], swt[38])));
        float k0 = fmaf(x, swt[ 9], fmaf(y, swt[12], fmaf(z, swt[15], swt[39])));
        float k1 = fmaf(x, swt[10], fmaf(y, swt[13], fmaf(z, swt[16], swt[40])));
        float k2 = fmaf(x, swt[11], fmaf(y, swt[14], fmaf(z, swt[17], swt[41])));
        float v0 = fmaf(x, swt[18], fmaf(y, swt[21], fmaf(z, swt[24], swt[42])));
        float v1 = fmaf(x, swt[19], fmaf(y, swt[22], fmaf(z, swt[25], swt[43])));
        float v2 = fmaf(x, swt[20], fmaf(y, swt[23], fmaf(z, swt[26], swt[44])));

        float* kp = u_kvs[wl][lane];
        *(float4*)kp       = make_float4(k0 * LOG2E, k1 * LOG2E, k2 * LOG2E, v0);
        *(float2*)(kp + 4) = make_float2(v1, v2);
        __syncwarp();

        float n0a = 0.f, n1a = 0.f, n2a = 0.f, d0 = 0.f, d1 = 0.f, d2 = 0.f;
#pragma unroll
        for (int j = 0; j < 32; j++) {
            const float* kj = u_kvs[wl][j];
            float4 a = *(const float4*)kj;
            float2 b = *(const float2*)(kj + 4);
            float e0 = ex2f(q0 * a.x);
            float e1 = ex2f(q1 * a.y);
            float e2 = ex2f(q2 * a.z);
            n0a = fmaf(e0, a.w, n0a); d0 += e0;
            n1a = fmaf(e1, b.x, n1a); d1 += e1;
            n2a = fmaf(e2, b.y, n2a); d2 += e2;
        }
        float o0 = __fdividef(n0a, d0);
        float o1 = __fdividef(n1a, d1);
        float o2 = __fdividef(n2a, d2);

        float b0 = fmaf(o0, swt[27], fmaf(o1, swt[30], fmaf(o2, swt[33], swt[45])));
        float b1 = fmaf(o0, swt[28], fmaf(o1, swt[31], fmaf(o2, swt[34], swt[46])));
        float b2 = fmaf(o0, swt[29], fmaf(o1, swt[32], fmaf(o2, swt[35], swt[47])));
        float matt = fmaxf(b0, fmaxf(b1, b2));

        float ssum = wredsum(matt);
        float wgt = matt / ssum;
        s_w[slot][lane] = wgt;

        const int m = npts[n];
        const float fm = (float)m;
        const float inv_m = 1.0f / fm;
        const bool act = lane < m;

        float wmx = wredmax(act ? -FLT_MAX : wgt);
        float wmn = wredmin(act ?  FLT_MAX : wgt);

        // 16-value reduce-scatter: V[0..13] masked moments, V[14]=x, V[15]=y
        float px = act ? x : 0.f, py = act ? y : 0.f;
        float pz = act ? z : 0.f, pI = act ? I : 0.f;
        float V[16] = { px*px, px*py, px*pz, px*pI, py*py, py*pz, py*pI,
                        pz*pz, pz*pI, pI*pI, px, py, pz, pI, x, y };
#pragma unroll
        for (int t = 0; t < 16; t++)
            V[t] += __shfl_xor_sync(0xffffffffu, V[t], 16);
        float W8[8];
#pragma unroll
        for (int t = 0; t < 8; t++) {
            bool hi = (lane & 8);
            float snd = hi ? V[t] : V[t + 8];
            float kp2 = hi ? V[t + 8] : V[t];
            W8[t] = kp2 + __shfl_xor_sync(0xffffffffu, snd, 8);
        }
        float W4[4];
#pragma unroll
        for (int t = 0; t < 4; t++) {
            bool hi = (lane & 4);
            float snd = hi ? W8[t] : W8[t + 4];
            float kp2 = hi ? W8[t + 4] : W8[t];
            W4[t] = kp2 + __shfl_xor_sync(0xffffffffu, snd, 4);
        }
        float W2[2];
#pragma unroll
        for (int t = 0; t < 2; t++) {
            bool hi = (lane & 2);
            float snd = hi ? W4[t] : W4[t + 2];
            float kp2 = hi ? W4[t + 2] : W4[t];
            W2[t] = kp2 + __shfl_xor_sync(0xffffffffu, snd, 2);
        }
        float fin;
        {
            bool hi = (lane & 1);
            float snd = hi ? W2[0] : W2[1];
            float kp2 = hi ? W2[1] : W2[0];
            fin = kp2 + __shfl_xor_sync(0xffffffffu, snd, 1);
        }
        float sz = wredsum(z);

        // scatter per-pillar scalars
        if (lane >= 26 && lane < 30) s_cst[slot][lane - 20] = fin;        // Sv -> [6..9]
        if (lane == 14) s_cst[slot][3] = fin * inv_m;                     // mx
        if (lane == 15) s_cst[slot][4] = fin * inv_m;                     // my
        if (lane == 16) s_cst[slot][5] = sz  * inv_m;                     // mz
        int4 cc = coors[n];
        if (lane == 0) s_cst[slot][0] = fmaf((float)cc.w, 0.2f, 0.1f);
        if (lane == 1) s_cst[slot][1] = fmaf((float)cc.z, 0.2f, -39.9f);
        if (lane == 2) s_cst[slot][2] = fmaf((float)cc.y, 4.0f, -1.0f);
        __syncwarp();

        const float* sqw = s_cst[slot];
        a0 += fin;                                   // lanes <14 meaningful
        a1 += tail_val(14 + lane, sqw, fm);          // slots 14..45
        if (lane < 19) a2 += tail_val(46 + lane, sqw, fm);  // 46..64
        __syncwarp();

        // overwrite Sv[0..2] with phase-B constants (Sv no longer needed)
        if (lane == 0) { s_cst[slot][6] = wmx; s_cst[slot][7] = wmn; s_cst[slot][8] = fm; }
        __syncwarp();
    }

    // block reduce + atomic
    {
        float* r = red[wl];
        if (lane < 14) r[lane] = a0;
        r[14 + lane] = a1;
        if (lane < 19) r[46 + lane] = a2;
    }
    __syncthreads();
    if (tid < 65) {
        double acc = 0.0;
#pragma unroll
        for (int w2 = 0; w2 < 8; w2++) acc += (double)red[w2][tid];
        atomicAdd(&g_mom[tid], acc);
        __threadfence();
    }
    __syncthreads();

    // ================= DEVICE BARRIER =================
    if (tid == 0) {
        __threadfence();
        atomicAdd(&g_arrive, 1u);
        while (atomicAdd(&g_arrive, 0u) < NBLK) __nanosleep(200);
    }
    __syncthreads();
    __threadfence();

    // ================= per-block BN fold (fp32), arrays overlay u_kvs =================
    float* smom = &u_kvs[0][0][0];   // 65
    float* sA   = smom + 80;         // 256, 16B aligned
    float* sG   = sA + 256;          // 384, 8B aligned
    float* sT   = sG + 384;          // 64,  8B aligned

    if (tid < 65) smom[tid] = (float)((volatile double*)g_mom)[tid];
    __syncthreads();
    if (tid < 64) {
        const int c = tid;
        float W[10];
#pragma unroll
        for (int r = 0; r < 10; r++) W[r] = pfn_w[r * 64 + c];
        float A[4] = { W[0]+W[4]+W[7], W[1]+W[5]+W[8], W[2]+W[6]+W[9], W[3] };
        float G[6] = { -(W[0]+W[7]), -(W[1]+W[8]), -(W[2]+W[9]), -W[4], -W[5], -W[6] };

        float S1 = 0.f;
#pragma unroll
        for (int d = 0; d < 4; d++) S1 += smom[10 + d] * A[d];
#pragma unroll
        for (int a = 0; a < 6; a++) S1 += smom[59 + a] * G[a];
        float mean = S1 * (1.0f / NMTOT);

        float E2 = 0.f;
        int pi = 0;
#pragma unroll
        for (int d = 0; d < 4; d++)
#pragma unroll
            for (int e = d; e < 4; e++)
                E2 += (d == e ? 1.f : 2.f) * A[d] * A[e] * smom[pi++];
#pragma unroll
        for (int a = 0; a < 6; a++)
#pragma unroll
            for (int d = 0; d < 4; d++)
                E2 += 2.f * G[a] * A[d] * smom[14 + a * 4 + d];
        int qi = 38;
#pragma unroll
        for (int a = 0; a < 6; a++)
#pragma unroll
            for (int b = a; b < 6; b++)
                E2 += (a == b ? 1.f : 2.f) * G[a] * G[b] * smom[qi++];
        E2 *= (1.0f / NMTOT);

        float var = E2 - mean * mean;
        float s = gamma[c] * rsqrtf(var + 1e-3f);
        float t = beta[c] - mean * s;
#pragma unroll
        for (int d = 0; d < 4; d++) sA[c * 4 + d] = A[d] * s;
#pragma unroll
        for (int a = 0; a < 6; a++) sG[a * 64 + c] = G[a] * s;
        sT[c] = t;
    }
    __syncthreads();

    // ================= PHASE B: pure-smem PFN + maxes =================
    float4 Aa = *(const float4*)&sA[(2 * lane) * 4];
    float4 Ab = *(const float4*)&sA[(2 * lane + 1) * 4];
    float2 Gv[6];
#pragma unroll
    for (int a = 0; a < 6; a++) Gv[a] = ((const float2*)(sG + 64 * a))[lane];
    float2 tv = ((const float2*)sT)[lane];
    const float tp0 = fmaxf(tv.x, 0.01f * tv.x);
    const float tp1 = fmaxf(tv.y, 0.01f * tv.y);

#pragma unroll 1
    for (int slot = wl; slot < P; slot += 8) {
        const int n = base + slot;
        const float* cst = s_cst[slot];
        const float fm_s = cst[8];
        const int   m    = (int)fm_s;
        const float wmmx = cst[6], wmmy = cst[7];

        float k0 = tv.x, k1 = tv.y;
#pragma unroll
        for (int a = 0; a < 6; a++) {
            float qa = cst[a];
            k0 = fmaf(qa, Gv[a].x, k0);
            k1 = fmaf(qa, Gv[a].y, k1);
        }

        float fm0, fm1, fa0, fa1;
        if (m < MPTS) {
            fm0 = tp0; fm1 = tp1;
            fa0 = (tp0 >= 0.f) ? tp0 * wmmx : tp0 * wmmy;
            fa1 = (tp1 >= 0.f) ? tp1 * wmmx : tp1 * wmmy;
        } else {
            fm0 = fm1 = fa0 = fa1 = -FLT_MAX;
        }

#pragma unroll 4
        for (int i = 0; i < m; i++) {
            float4 p = s_feat[slot][i];
            float wi = s_w[slot][i];
            float r0 = fmaf(p.x, Aa.x, fmaf(p.y, Aa.y,
                       fmaf(p.z, Aa.z, fmaf(p.w, Aa.w, k0))));
            float u0 = fmaxf(r0, 0.01f * r0);
            fm0 = fmaxf(fm0, u0);
            fa0 = fmaxf(fa0, wi * u0);
            float r1 = fmaf(p.x, Ab.x, fmaf(p.y, Ab.y,
                       fmaf(p.z, Ab.z, fmaf(p.w, Ab.w, k1))));
            float u1 = fmaxf(r1, 0.01f * r1);
            fm1 = fmaxf(fm1, u1);
            fa1 = fmaxf(fa1, wi * u1);
        }
        ((float2*)(out + n * 64))[lane] =
            make_float2(0.5f * (fa0 + fm0), 0.5f * (fa1 + fm1));
    }

    // ================= last block resets counters for next replay =================
    __syncthreads();
    if (tid == 0) {
        __threadfence();
        unsigned d = atomicAdd(&g_done, 1u);
        if (d == NBLK - 1) {
            for (int i = 0; i < 65; i++) g_mom[i] = 0.0;
            g_arrive = 0u;
            g_done = 0u;
            __threadfence();
        }
    }
}

// ---------------- launch ----------------
extern "C" void kernel_launch(void* const* d_in, const int* in_sizes, int n_in,
                              void* d_out, int out_size)
{
    const float4* feat  = (const float4*)d_in[0];
    const int*    npts  = (const int*)  d_in[1];
    const int4*   coors = (const int4*) d_in[2];
    const float*  pfn_w = (const float*)d_in[3];
    const float*  gamma = (const float*)d_in[4];
    const float*  beta  = (const float*)d_in[5];
    const float*  wq    = (const float*)d_in[6];
    const float*  wk    = (const float*)d_in[7];
    const float*  wv    = (const float*)d_in[8];
    const float*  wo    = (const float*)d_in[9];
    const float*  bq    = (const float*)d_in[10];
    const float*  bk    = (const float*)d_in[11];
    const float*  bv    = (const float*)d_in[12];
    const float*  bo    = (const float*)d_in[13];
    float* out = (float*)d_out;

    k_fused<<<NBLK, 256>>>(feat, npts, coors, out, wq, wk, wv, wo,
                           bq, bk, bv, bo, pfn_w, gamma, beta);
}

// round 15
// speedup vs baseline: 1.6142x; 1.6142x over previous
#include <cuda_runtime.h>
#include <cfloat>
#include <math.h>

#define NPIL 30000
#define MPTS 32
#define NBLK 592
#define PPB  51                       // 592*51 = 30192 >= 30000
#define NMTOT (30000.0f * 32.0f)
#define LOG2E 1.4426950408889634f

// dynamic smem layout (bytes)
#define FEAT_OFF 0                    // float4 [PPB][32]   26112
#define UKVS_OFF 26112                // float  [8][32][16] 16384 (A at +0, B at +8)
#define SW_OFF   42496                // float  [PPB][32]    6528
#define SCST_OFF 49024                // float  [PPB][10]    2040 (+8 pad)
#define RED_OFF  51072                // float  [8][65]      2080
#define SWT_OFF  53152                // float  [48]          192
#define SMEM_TOTAL 53376

// ---------------- globals (zero-init; counters reset by last block) ----------------
__device__ double   g_mom[65];
__device__ unsigned g_arrive;
__device__ unsigned g_done;

// QQ triangular index tables (l-38 -> (a,b))
__constant__ signed char d_qa[21] = {0,0,0,0,0,0,1,1,1,1,1,2,2,2,2,3,3,3,4,4,5};
__constant__ signed char d_qb[21] = {0,1,2,3,4,5,1,2,3,4,5,2,3,4,5,3,4,5,4,5,5};

__device__ __forceinline__ float ex2f(float x) {
    float y; asm("ex2.approx.f32 %0, %1;" : "=f"(y) : "f"(x)); return y;
}
__device__ __forceinline__ float wredsum(float v) {
#pragma unroll
    for (int o = 16; o; o >>= 1) v += __shfl_xor_sync(0xffffffffu, v, o);
    return v;
}
__device__ __forceinline__ float wredmax(float v) {
#pragma unroll
    for (int o = 16; o; o >>= 1) v = fmaxf(v, __shfl_xor_sync(0xffffffffu, v, o));
    return v;
}
__device__ __forceinline__ float wredmin(float v) {
#pragma unroll
    for (int o = 16; o; o >>= 1) v = fminf(v, __shfl_xor_sync(0xffffffffu, v, o));
    return v;
}
__device__ __forceinline__ float tail_val(int l, const float* sqw, float fm) {
    if (l < 38) { int u = l - 14; return sqw[u >> 2] * sqw[6 + (u & 3)]; }
    if (l < 59) { int u = l - 38; return fm * sqw[(int)d_qa[u]] * sqw[(int)d_qb[u]]; }
    return fm * sqw[l - 59];
}

// per-pillar epilogue: weights, reductions, moment accumulation, phase-B consts
__device__ __forceinline__ void epilogue(
    int slot, int n, float matt, int m, bool acc,
    const int4* __restrict__ coors,
    float4* s_feat, float* s_w, float* s_cst,
    float& a0, float& a1, float& a2, int lane)
{
    int4 cc = coors[n];                       // issue LDG early
    float ssum = wredsum(matt);
    float wgt = matt / ssum;
    s_w[slot * 32 + lane] = wgt;

    float4 f = s_feat[slot * 32 + lane];
    const float x = f.x, y = f.y, z = f.z, I = f.w;
    const float fm = (float)m;
    const float inv_m = 1.0f / fm;
    const bool act = lane < m;

    float wmx = wredmax(act ? -FLT_MAX : wgt);
    float wmn = wredmin(act ?  FLT_MAX : wgt);

    float px = act ? x : 0.f, py = act ? y : 0.f;
    float pz = act ? z : 0.f, pI = act ? I : 0.f;
    float V[16] = { px*px, px*py, px*pz, px*pI, py*py, py*pz, py*pI,
                    pz*pz, pz*pI, pI*pI, px, py, pz, pI, x, y };
#pragma unroll
    for (int t = 0; t < 16; t++)
        V[t] += __shfl_xor_sync(0xffffffffu, V[t], 16);
    float W8[8];
#pragma unroll
    for (int t = 0; t < 8; t++) {
        bool hi = (lane & 8);
        float snd = hi ? V[t] : V[t + 8];
        float kp2 = hi ? V[t + 8] : V[t];
        W8[t] = kp2 + __shfl_xor_sync(0xffffffffu, snd, 8);
    }
    float W4[4];
#pragma unroll
    for (int t = 0; t < 4; t++) {
        bool hi = (lane & 4);
        float snd = hi ? W8[t] : W8[t + 4];
        float kp2 = hi ? W8[t + 4] : W8[t];
        W4[t] = kp2 + __shfl_xor_sync(0xffffffffu, snd, 4);
    }
    float W2[2];
#pragma unroll
    for (int t = 0; t < 2; t++) {
        bool hi = (lane & 2);
        float snd = hi ? W4[t] : W4[t + 2];
        float kp2 = hi ? W4[t + 2] : W4[t];
        W2[t] = kp2 + __shfl_xor_sync(0xffffffffu, snd, 2);
    }
    float fin;
    {
        bool hi = (lane & 1);
        float snd = hi ? W2[0] : W2[1];
        float kp2 = hi ? W2[1] : W2[0];
        fin = kp2 + __shfl_xor_sync(0xffffffffu, snd, 1);
    }
    float sz = wredsum(z);

    float* cst = s_cst + slot * 10;
    if (lane >= 26 && lane < 30) cst[lane - 20] = fin;    // Sv -> [6..9]
    if (lane == 14) cst[3] = fin * inv_m;                 // mx
    if (lane == 15) cst[4] = fin * inv_m;                 // my
    if (lane == 16) cst[5] = sz  * inv_m;                 // mz
    if (lane == 0) cst[0] = fmaf((float)cc.w, 0.2f, 0.1f);
    if (lane == 1) cst[1] = fmaf((float)cc.z, 0.2f, -39.9f);
    if (lane == 2) cst[2] = fmaf((float)cc.y, 4.0f, -1.0f);
    __syncwarp();

    if (acc) {
        const float* sqw = cst;
        a0 += fin;
        a1 += tail_val(14 + lane, sqw, fm);
        if (lane < 19) a2 += tail_val(46 + lane, sqw, fm);
    }
    __syncwarp();
    if (lane == 0) { cst[6] = wmx; cst[7] = wmn; cst[8] = fm; }
    __syncwarp();
}

// ---------------- single persistent kernel ----------------
__global__ __launch_bounds__(256, 4) void k_fused(
    const float4* __restrict__ feat, const int* __restrict__ npts,
    const int4*  __restrict__ coors, float* __restrict__ out,
    const float* __restrict__ wq, const float* __restrict__ wk,
    const float* __restrict__ wv, const float* __restrict__ wo,
    const float* __restrict__ bq, const float* __restrict__ bk,
    const float* __restrict__ bv, const float* __restrict__ bo,
    const float* __restrict__ pfn_w,
    const float* __restrict__ gamma, const float* __restrict__ beta)
{
    extern __shared__ __align__(16) char smem[];
    float4* s_feat = (float4*)(smem + FEAT_OFF);
    float*  u_kvs  = (float*)(smem + UKVS_OFF);
    float*  s_w    = (float*)(smem + SW_OFF);
    float*  s_cst  = (float*)(smem + SCST_OFF);
    float*  red    = (float*)(smem + RED_OFF);
    float*  swt    = (float*)(smem + SWT_OFF);

    const int tid  = threadIdx.x;
    const int wl   = tid >> 5;
    const int lane = tid & 31;
    const int base = blockIdx.x * PPB;
    const int rem  = NPIL - base;
    const int P    = rem > 0 ? (rem < PPB ? rem : PPB) : 0;

    {   // stage small weights
        int t = tid;
        if      (t <  9) swt[t] = wq[t];
        else if (t < 18) swt[t] = wk[t - 9];
        else if (t < 27) swt[t] = wv[t - 18];
        else if (t < 36) swt[t] = wo[t - 27];
        else if (t < 39) swt[t] = bq[t - 36];
        else if (t < 42) swt[t] = bk[t - 39];
        else if (t < 45) swt[t] = bv[t - 42];
        else if (t < 48) swt[t] = bo[t - 45];
    }
    __syncthreads();

    // ================= PHASE A: two pillars per warp-pass =================
    float a0 = 0.f, a1 = 0.f, a2 = 0.f;
    float* kvw = u_kvs + wl * 512;     // this warp's [32][16] buffer

    int s = wl;
#pragma unroll 1
    for (; s < P; s += 16) {
        const int slotA = s;
        const bool doB  = (s + 8) < P;
        const int slotB = doB ? s + 8 : s;
        const int nA = base + slotA;
        const int nB = base + slotB;

        float4 fA = feat[nA * MPTS + lane];
        float4 fB = feat[nB * MPTS + lane];
        int mA = npts[nA];
        int mB = npts[nB];
        s_feat[slotA * 32 + lane] = fA;
        if (doB) s_feat[slotB * 32 + lane] = fB;

        // qkv for A
        float qA0, qA1, qA2;
        {
            const float x = fA.x, y = fA.y, z = fA.z;
            qA0 = fmaf(x, swt[0], fmaf(y, swt[3], fmaf(z, swt[6], swt[36])));
            qA1 = fmaf(x, swt[1], fmaf(y, swt[4], fmaf(z, swt[7], swt[37])));
            qA2 = fmaf(x, swt[2], fmaf(y, swt[5], fmaf(z, swt[8], swt[38])));
            float k0 = fmaf(x, swt[ 9], fmaf(y, swt[12], fmaf(z, swt[15], swt[39])));
            float k1 = fmaf(x, swt[10], fmaf(y, swt[13], fmaf(z, swt[16], swt[40])));
            float k2 = fmaf(x, swt[11], fmaf(y, swt[14], fmaf(z, swt[17], swt[41])));
            float v0 = fmaf(x, swt[18], fmaf(y, swt[21], fmaf(z, swt[24], swt[42])));
            float v1 = fmaf(x, swt[19], fmaf(y, swt[22], fmaf(z, swt[25], swt[43])));
            float v2 = fmaf(x, swt[20], fmaf(y, swt[23], fmaf(z, swt[26], swt[44])));
            float* kp = kvw + lane * 16;
            *(float4*)kp       = make_float4(k0 * LOG2E, k1 * LOG2E, k2 * LOG2E, v0);
            *(float2*)(kp + 4) = make_float2(v1, v2);
        }
        // qkv for B
        float qB0, qB1, qB2;
        {
            const float x = fB.x, y = fB.y, z = fB.z;
            qB0 = fmaf(x, swt[0], fmaf(y, swt[3], fmaf(z, swt[6], swt[36])));
            qB1 = fmaf(x, swt[1], fmaf(y, swt[4], fmaf(z, swt[7], swt[37])));
            qB2 = fmaf(x, swt[2], fmaf(y, swt[5], fmaf(z, swt[8], swt[38])));
            float k0 = fmaf(x, swt[ 9], fmaf(y, swt[12], fmaf(z, swt[15], swt[39])));
            float k1 = fmaf(x, swt[10], fmaf(y, swt[13], fmaf(z, swt[16], swt[40])));
            float k2 = fmaf(x, swt[11], fmaf(y, swt[14], fmaf(z, swt[17], swt[41])));
            float v0 = fmaf(x, swt[18], fmaf(y, swt[21], fmaf(z, swt[24], swt[42])));
            float v1 = fmaf(x, swt[19], fmaf(y, swt[22], fmaf(z, swt[25], swt[43])));
            float v2 = fmaf(x, swt[20], fmaf(y, swt[23], fmaf(z, swt[26], swt[44])));
            float* kp = kvw + lane * 16 + 8;
            *(float4*)kp       = make_float4(k0 * LOG2E, k1 * LOG2E, k2 * LOG2E, v0);
            *(float2*)(kp + 4) = make_float2(v1, v2);
        }
        __syncwarp();

        // interleaved exp loops: 6 independent MUFU chains
        float nA0 = 0.f, nA1 = 0.f, nA2 = 0.f, dA0 = 0.f, dA1 = 0.f, dA2 = 0.f;
        float nB0 = 0.f, nB1 = 0.f, nB2 = 0.f, dB0 = 0.f, dB1 = 0.f, dB2 = 0.f;
#pragma unroll 8
        for (int j = 0; j < 32; j++) {
            const float* kj = kvw + j * 16;
            float4 a  = *(const float4*)kj;
            float2 a2v = *(const float2*)(kj + 4);
            float4 b  = *(const float4*)(kj + 8);
            float2 b2v = *(const float2*)(kj + 12);
            float eA0 = ex2f(qA0 * a.x);
            float eA1 = ex2f(qA1 * a.y);
            float eA2 = ex2f(qA2 * a.z);
            float eB0 = ex2f(qB0 * b.x);
            float eB1 = ex2f(qB1 * b.y);
            float eB2 = ex2f(qB2 * b.z);
            nA0 = fmaf(eA0, a.w,   nA0); dA0 += eA0;
            nA1 = fmaf(eA1, a2v.x, nA1); dA1 += eA1;
            nA2 = fmaf(eA2, a2v.y, nA2); dA2 += eA2;
            nB0 = fmaf(eB0, b.w,   nB0); dB0 += eB0;
            nB1 = fmaf(eB1, b2v.x, nB1); dB1 += eB1;
            nB2 = fmaf(eB2, b2v.y, nB2); dB2 += eB2;
        }
        float mattA, mattB;
        {
            float o0 = __fdividef(nA0, dA0);
            float o1 = __fdividef(nA1, dA1);
            float o2 = __fdividef(nA2, dA2);
            float b0 = fmaf(o0, swt[27], fmaf(o1, swt[30], fmaf(o2, swt[33], swt[45])));
            float b1 = fmaf(o0, swt[28], fmaf(o1, swt[31], fmaf(o2, swt[34], swt[46])));
            float b2 = fmaf(o0, swt[29], fmaf(o1, swt[32], fmaf(o2, swt[35], swt[47])));
            mattA = fmaxf(b0, fmaxf(b1, b2));
        }
        {
            float o0 = __fdividef(nB0, dB0);
            float o1 = __fdividef(nB1, dB1);
            float o2 = __fdividef(nB2, dB2);
            float b0 = fmaf(o0, swt[27], fmaf(o1, swt[30], fmaf(o2, swt[33], swt[45])));
            float b1 = fmaf(o0, swt[28], fmaf(o1, swt[31], fmaf(o2, swt[34], swt[46])));
            float b2 = fmaf(o0, swt[29], fmaf(o1, swt[32], fmaf(o2, swt[35], swt[47])));
            mattB = fmaxf(b0, fmaxf(b1, b2));
        }

        epilogue(slotA, nA, mattA, mA, true, coors, s_feat, s_w, s_cst, a0, a1, a2, lane);
        epilogue(slotB, nB, mattB, mB, doB,  coors, s_feat, s_w, s_cst, a0, a1, a2, lane);
    }

    // block reduce + atomic
    {
        float* r = red + wl * 65;
        if (lane < 14) r[lane] = a0;
        r[14 + lane] = a1;
        if (lane < 19) r[46 + lane] = a2;
    }
    __syncthreads();
    if (tid < 65) {
        double acc = 0.0;
#pragma unroll
        for (int w2 = 0; w2 < 8; w2++) acc += (double)red[w2 * 65 + tid];
        atomicAdd(&g_mom[tid], acc);
        __threadfence();
    }
    __syncthreads();

    // ================= DEVICE BARRIER =================
    if (tid == 0) {
        __threadfence();
        atomicAdd(&g_arrive, 1u);
        while (atomicAdd(&g_arrive, 0u) < NBLK) __nanosleep(200);
    }
    __syncthreads();
    __threadfence();

    // ================= per-block BN fold (fp32), arrays overlay u_kvs =================
    float* smom = u_kvs;             // 65
    float* sA   = smom + 80;         // 256, 16B aligned
    float* sG   = sA + 256;          // 384, 8B aligned
    float* sT   = sG + 384;          // 64,  8B aligned

    if (tid < 65) smom[tid] = (float)((volatile double*)g_mom)[tid];
    __syncthreads();
    if (tid < 64) {
        const int c = tid;
        float W[10];
#pragma unroll
        for (int r = 0; r < 10; r++) W[r] = pfn_w[r * 64 + c];
        float A[4] = { W[0]+W[4]+W[7], W[1]+W[5]+W[8], W[2]+W[6]+W[9], W[3] };
        float G[6] = { -(W[0]+W[7]), -(W[1]+W[8]), -(W[2]+W[9]), -W[4], -W[5], -W[6] };

        float S1 = 0.f;
#pragma unroll
        for (int d = 0; d < 4; d++) S1 += smom[10 + d] * A[d];
#pragma unroll
        for (int a = 0; a < 6; a++) S1 += smom[59 + a] * G[a];
        float mean = S1 * (1.0f / NMTOT);

        float E2 = 0.f;
        int pi = 0;
#pragma unroll
        for (int d = 0; d < 4; d++)
#pragma unroll
            for (int e = d; e < 4; e++)
                E2 += (d == e ? 1.f : 2.f) * A[d] * A[e] * smom[pi++];
#pragma unroll
        for (int a = 0; a < 6; a++)
#pragma unroll
            for (int d = 0; d < 4; d++)
                E2 += 2.f * G[a] * A[d] * smom[14 + a * 4 + d];
        int qi = 38;
#pragma unroll
        for (int a = 0; a < 6; a++)
#pragma unroll
            for (int b = a; b < 6; b++)
                E2 += (a == b ? 1.f : 2.f) * G[a] * G[b] * smom[qi++];
        E2 *= (1.0f / NMTOT);

        float var = E2 - mean * mean;
        float sc = gamma[c] * rsqrtf(var + 1e-3f);
        float t = beta[c] - mean * sc;
#pragma unroll
        for (int d = 0; d < 4; d++) sA[c * 4 + d] = A[d] * sc;
#pragma unroll
        for (int a = 0; a < 6; a++) sG[a * 64 + c] = G[a] * sc;
        sT[c] = t;
    }
    __syncthreads();

    // ================= PHASE B: pure-smem PFN + maxes =================
    float4 Aa = *(const float4*)&sA[(2 * lane) * 4];
    float4 Ab = *(const float4*)&sA[(2 * lane + 1) * 4];
    float2 Gv[6];
#pragma unroll
    for (int a = 0; a < 6; a++) Gv[a] = ((const float2*)(sG + 64 * a))[lane];
    float2 tv = ((const float2*)sT)[lane];
    const float tp0 = fmaxf(tv.x, 0.01f * tv.x);
    const float tp1 = fmaxf(tv.y, 0.01f * tv.y);

#pragma unroll 1
    for (int slot = wl; slot < P; slot += 8) {
        const int n = base + slot;
        const float* cst = s_cst + slot * 10;
        const float fm_s = cst[8];
        const int   m    = (int)fm_s;
        const float wmmx = cst[6], wmmy = cst[7];

        float k0 = tv.x, k1 = tv.y;
#pragma unroll
        for (int a = 0; a < 6; a++) {
            float qa = cst[a];
            k0 = fmaf(qa, Gv[a].x, k0);
            k1 = fmaf(qa, Gv[a].y, k1);
        }

        float fm0, fm1, fa0, fa1;
        if (m < MPTS) {
            fm0 = tp0; fm1 = tp1;
            fa0 = (tp0 >= 0.f) ? tp0 * wmmx : tp0 * wmmy;
            fa1 = (tp1 >= 0.f) ? tp1 * wmmx : tp1 * wmmy;
        } else {
            fm0 = fm1 = fa0 = fa1 = -FLT_MAX;
        }

#pragma unroll 4
        for (int i = 0; i < m; i++) {
            float4 p = s_feat[slot * 32 + i];
            float wi = s_w[slot * 32 + i];
            float r0 = fmaf(p.x, Aa.x, fmaf(p.y, Aa.y,
                       fmaf(p.z, Aa.z, fmaf(p.w, Aa.w, k0))));
            float u0 = fmaxf(r0, 0.01f * r0);
            fm0 = fmaxf(fm0, u0);
            fa0 = fmaxf(fa0, wi * u0);
            float r1 = fmaf(p.x, Ab.x, fmaf(p.y, Ab.y,
                       fmaf(p.z, Ab.z, fmaf(p.w, Ab.w, k1))));
            float u1 = fmaxf(r1, 0.01f * r1);
            fm1 = fmaxf(fm1, u1);
            fa1 = fmaxf(fa1, wi * u1);
        }
        ((float2*)(out + n * 64))[lane] =
            make_float2(0.5f * (fa0 + fm0), 0.5f * (fa1 + fm1));
    }

    // ================= last block resets counters for next replay =================
    __syncthreads();
    if (tid == 0) {
        __threadfence();
        unsigned d = atomicAdd(&g_done, 1u);
        if (d == NBLK - 1) {
            for (int i = 0; i < 65; i++) g_mom[i] = 0.0;
            g_arrive = 0u;
            g_done = 0u;
            __threadfence();
        }
    }
}

// ---------------- launch ----------------
extern "C" void kernel_launch(void* const* d_in, const int* in_sizes, int n_in,
                              void* d_out, int out_size)
{
    const float4* feat  = (const float4*)d_in[0];
    const int*    npts  = (const int*)  d_in[1];
    const int4*   coors = (const int4*) d_in[2];
    const float*  pfn_w = (const float*)d_in[3];
    const float*  gamma = (const float*)d_in[4];
    const float*  beta  = (const float*)d_in[5];
    const float*  wq    = (const float*)d_in[6];
    const float*  wk    = (const float*)d_in[7];
    const float*  wv    = (const float*)d_in[8];
    const float*  wo    = (const float*)d_in[9];
    const float*  bq    = (const float*)d_in[10];
    const float*  bk    = (const float*)d_in[11];
    const float*  bv    = (const float*)d_in[12];
    const float*  bo    = (const float*)d_in[13];
    float* out = (float*)d_out;

    cudaFuncSetAttribute(k_fused, cudaFuncAttributeMaxDynamicSharedMemorySize,
                         SMEM_TOTAL);
    k_fused<<<NBLK, 256, SMEM_TOTAL>>>(feat, npts, coors, out, wq, wk, wv, wo,
                                       bq, bk, bv, bo, pfn_w, gamma, beta);
}